// round 2
// baseline (speedup 1.0000x reference)
#include <cuda_runtime.h>
#include <cstdint>
#include <cstddef>

// Problem dims
#define B_DIM 8192
#define IN_DIM 2048
#define HID 2048
#define KDIM 4096   // IN + HID
#define NDIM 8192   // 4 * HID

// GEMM tiling
#define BM 128
#define BN 128
#define BK 32
#define KT (KDIM / BK)   // 128 k-tiles

// Smem strides (floats), chosen for conflict-free fragment loads and 16B-aligned rows
#define AS_STRIDE 36     // bank(m*36+k) = (4m+k)%32 -> distinct per lane
#define BS_STRIDE 136    // bank(k*136+n) = (8k+n)%32 -> distinct per lane
#define A_STAGE (BM * AS_STRIDE)          // 4608 floats
#define B_STAGE (BK * BS_STRIDE)          // 4352 floats
#define STAGE_FLOATS (A_STAGE + B_STAGE)  // 8960 floats
#define SMEM_FLOATS (2 * STAGE_FLOATS)    // 17920 floats = 71680 B

// 256 MB scratch for pre-activation gates z = [B, 4*HID]
__device__ float g_z[(size_t)B_DIM * NDIM];

__device__ __forceinline__ void cpasync16(void* smem_ptr, const void* gptr) {
    uint32_t s = (uint32_t)__cvta_generic_to_shared(smem_ptr);
    asm volatile("cp.async.cg.shared.global [%0], [%1], 16;\n" :: "r"(s), "l"(gptr));
}

__device__ __forceinline__ uint32_t f2tf(float f) {
    uint32_t u;
    asm("cvt.rna.tf32.f32 %0, %1;\n" : "=r"(u) : "f"(f));
    return u;
}

__device__ __forceinline__ void mma_tf32(float* c,
                                         uint32_t a0, uint32_t a1, uint32_t a2, uint32_t a3,
                                         uint32_t b0, uint32_t b1) {
    asm volatile(
        "mma.sync.aligned.m16n8k8.row.col.f32.tf32.tf32.f32 "
        "{%0,%1,%2,%3}, {%4,%5,%6,%7}, {%8,%9}, {%0,%1,%2,%3};\n"
        : "+f"(c[0]), "+f"(c[1]), "+f"(c[2]), "+f"(c[3])
        : "r"(a0), "r"(a1), "r"(a2), "r"(a3), "r"(b0), "r"(b1));
}

__global__ __launch_bounds__(256, 2) void lstm_gemm(
    const float* __restrict__ x, const float* __restrict__ h,
    const float* __restrict__ Wf, const float* __restrict__ Wi,
    const float* __restrict__ Wc, const float* __restrict__ Wo)
{
    extern __shared__ float smem[];

    const int m_base = blockIdx.y * BM;
    const int n_glob = blockIdx.x * BN;
    const int gate   = n_glob >> 11;          // 2048-wide gates
    const int n_loc  = n_glob & 2047;
    const float* W = (gate == 0) ? Wf : (gate == 1) ? Wi : (gate == 2) ? Wc : Wo;

    const int tid  = threadIdx.x;
    const int warp = tid >> 5;
    const int lane = tid & 31;
    const int wm = (warp & 3) * 32;   // 4 warps along M
    const int wn = (warp >> 2) * 64;  // 2 warps along N
    const int lr = lane >> 2;         // 0..7
    const int lc = lane & 3;          // 0..3

    float acc[2][8][4];
    #pragma unroll
    for (int mf = 0; mf < 2; ++mf)
        #pragma unroll
        for (int nf = 0; nf < 8; ++nf)
            #pragma unroll
            for (int i = 0; i < 4; ++i)
                acc[mf][nf][i] = 0.0f;

    // gmem->smem load index assignments
    const int a_tr = tid >> 3;          // 0..31 (row within 32-row slab)
    const int a_tc = (tid & 7) * 4;     // 0,4,...,28 (col, 4 floats = 16B)
    const int b_tr = tid >> 5;          // 0..7
    const int b_tc = (tid & 31) * 4;    // 0..124

    auto load_stage = [&](int s, int kk) {
        float* As = smem + s * STAGE_FLOATS;
        float* Bs = smem + s * STAGE_FLOATS + A_STAGE;
        const float* ap;
        int ko;
        if (kk < IN_DIM) { ap = x; ko = kk; } else { ap = h; ko = kk - IN_DIM; }
        #pragma unroll
        for (int it = 0; it < 4; ++it) {
            int r = a_tr + it * 32;
            cpasync16(&As[r * AS_STRIDE + a_tc],
                      ap + (size_t)(m_base + r) * IN_DIM + ko + a_tc);
        }
        #pragma unroll
        for (int it = 0; it < 4; ++it) {
            int r = b_tr + it * 8;
            cpasync16(&Bs[r * BS_STRIDE + b_tc],
                      W + (size_t)(kk + r) * HID + n_loc + b_tc);
        }
    };

    auto compute_stage = [&](int s) {
        const float* As = smem + s * STAGE_FLOATS;
        const float* Bs = smem + s * STAGE_FLOATS + A_STAGE;
        #pragma unroll
        for (int ks = 0; ks < 4; ++ks) {
            const int k0 = ks * 8;
            uint32_t af[2][4];
            #pragma unroll
            for (int mf = 0; mf < 2; ++mf) {
                int r0 = wm + mf * 16 + lr;
                af[mf][0] = f2tf(As[(r0)     * AS_STRIDE + k0 + lc]);
                af[mf][1] = f2tf(As[(r0 + 8) * AS_STRIDE + k0 + lc]);
                af[mf][2] = f2tf(As[(r0)     * AS_STRIDE + k0 + lc + 4]);
                af[mf][3] = f2tf(As[(r0 + 8) * AS_STRIDE + k0 + lc + 4]);
            }
            #pragma unroll
            for (int nf = 0; nf < 8; ++nf) {
                int nb = wn + nf * 8 + lr;
                uint32_t b0 = f2tf(Bs[(k0 + lc)     * BS_STRIDE + nb]);
                uint32_t b1 = f2tf(Bs[(k0 + lc + 4) * BS_STRIDE + nb]);
                mma_tf32(acc[0][nf], af[0][0], af[0][1], af[0][2], af[0][3], b0, b1);
                mma_tf32(acc[1][nf], af[1][0], af[1][1], af[1][2], af[1][3], b0, b1);
            }
        }
    };

    load_stage(0, 0);
    asm volatile("cp.async.commit_group;\n");

    for (int kt = 0; kt < KT; ++kt) {
        asm volatile("cp.async.wait_group 0;\n");
        __syncthreads();
        if (kt + 1 < KT) load_stage((kt + 1) & 1, (kt + 1) * BK);
        asm volatile("cp.async.commit_group;\n");
        compute_stage(kt & 1);
        __syncthreads();
    }

    // epilogue: write z tile to scratch
    #pragma unroll
    for (int mf = 0; mf < 2; ++mf) {
        #pragma unroll
        for (int nf = 0; nf < 8; ++nf) {
            int row = m_base + wm + mf * 16 + lr;
            int col = n_glob + wn + nf * 8 + 2 * lc;
            float2 v0 = make_float2(acc[mf][nf][0], acc[mf][nf][1]);
            float2 v1 = make_float2(acc[mf][nf][2], acc[mf][nf][3]);
            *(float2*)&g_z[(size_t)row * NDIM + col]       = v0;
            *(float2*)&g_z[(size_t)(row + 8) * NDIM + col] = v1;
        }
    }
}

__device__ __forceinline__ float sigm(float v) { return 1.0f / (1.0f + expf(-v)); }

__global__ __launch_bounds__(256) void lstm_act(
    const float* __restrict__ c_prev,
    const float* __restrict__ bf, const float* __restrict__ bi,
    const float* __restrict__ bc, const float* __restrict__ bo,
    float* __restrict__ out)
{
    size_t i = (size_t)blockIdx.x * blockDim.x + threadIdx.x;   // over B*HID/4
    int m  = (int)(i / (HID / 4));
    int n4 = (int)(i % (HID / 4)) * 4;

    size_t zb = (size_t)m * NDIM + n4;
    float4 zf = *(const float4*)&g_z[zb];
    float4 zi = *(const float4*)&g_z[zb + 2048];
    float4 zc = *(const float4*)&g_z[zb + 4096];
    float4 zo = *(const float4*)&g_z[zb + 6144];
    float4 cp = *(const float4*)&c_prev[(size_t)m * HID + n4];
    float4 vf = *(const float4*)&bf[n4];
    float4 vi = *(const float4*)&bi[n4];
    float4 vc = *(const float4*)&bc[n4];
    float4 vo = *(const float4*)&bo[n4];

    float zfa[4] = {zf.x, zf.y, zf.z, zf.w};
    float zia[4] = {zi.x, zi.y, zi.z, zi.w};
    float zca[4] = {zc.x, zc.y, zc.z, zc.w};
    float zoa[4] = {zo.x, zo.y, zo.z, zo.w};
    float cpa[4] = {cp.x, cp.y, cp.z, cp.w};
    float bfa[4] = {vf.x, vf.y, vf.z, vf.w};
    float bia[4] = {vi.x, vi.y, vi.z, vi.w};
    float bca[4] = {vc.x, vc.y, vc.z, vc.w};
    float boa[4] = {vo.x, vo.y, vo.z, vo.w};

    float ha[4], ca[4];
    #pragma unroll
    for (int j = 0; j < 4; ++j) {
        float f_t = sigm(zfa[j] + bfa[j]);
        float i_t = sigm(zia[j] + bia[j]);
        float cop = tanhf(zca[j] + bca[j]);
        float c_t = cpa[j] * f_t + i_t * cop;
        float o_t = sigm(zoa[j] + boa[j]);
        ca[j] = c_t;
        ha[j] = o_t * tanhf(c_t);
    }

    float4 h4 = make_float4(ha[0], ha[1], ha[2], ha[3]);
    float4 c4 = make_float4(ca[0], ca[1], ca[2], ca[3]);
    size_t ob = (size_t)m * HID + n4;
    *(float4*)&out[ob] = h4;
    *(float4*)&out[(size_t)B_DIM * HID + ob] = c4;
}

extern "C" void kernel_launch(void* const* d_in, const int* in_sizes, int n_in,
                              void* d_out, int out_size) {
    const float* x      = (const float*)d_in[0];
    const float* h_prev = (const float*)d_in[1];
    const float* c_prev = (const float*)d_in[2];
    // d_in[3] embedding_vec: ignored in vanilla mode
    const float* Wf = (const float*)d_in[4];
    const float* Wi = (const float*)d_in[5];
    const float* Wc = (const float*)d_in[6];
    const float* Wo = (const float*)d_in[7];
    const float* bf = (const float*)d_in[8];
    const float* bi = (const float*)d_in[9];
    const float* bc = (const float*)d_in[10];
    const float* bo = (const float*)d_in[11];
    float* out = (float*)d_out;

    const int smem_bytes = SMEM_FLOATS * 4;  // 71680
    cudaFuncSetAttribute(lstm_gemm, cudaFuncAttributeMaxDynamicSharedMemorySize, smem_bytes);

    dim3 grid(NDIM / BN, B_DIM / BM);  // (64, 64)
    lstm_gemm<<<grid, 256, smem_bytes>>>(x, h_prev, Wf, Wi, Wc, Wo);

    int total4 = B_DIM * HID / 4;      // 4,194,304
    lstm_act<<<total4 / 256, 256>>>(c_prev, bf, bi, bc, bo, out);
}

// round 4
// speedup vs baseline: 1.8317x; 1.8317x over previous
#include <cuda_runtime.h>
#include <cuda_fp16.h>
#include <cstdint>
#include <cstddef>

#define B_DIM 8192
#define HID 2048
#define KDIM 4096
#define NDIM 8192

#define BM 128
#define BK 32
#define KT (KDIM / BK)     // 128
#define NLOC 64            // within-gate cols per CTA (x4 gates = 256 smem cols)
#define STAGES 4

#define A_ROW_B 80         // 32 halves + 8 pad  (80/16=5 -> 16B aligned rows)
#define B_ROW_B 528        // 256 halves + 8 pad (528/16=33)
#define A_BYTES (BM * A_ROW_B)        // 10240
#define B_BYTES (BK * B_ROW_B)        // 16896
#define STAGE_B (A_BYTES + B_BYTES)   // 27136
#define SMEM_DYN (STAGES * STAGE_B)   // 108544

// fp16 scratch: concat(x,h) [8192][4096] and W [4][4096][2048]
__device__ __half g_xh[(size_t)B_DIM * KDIM];
__device__ __half g_w16[(size_t)4 * KDIM * HID];

// ---------------- helpers ----------------
__device__ __forceinline__ uint32_t s2u(const void* p) {
    uint32_t a;
    asm("{.reg .u64 t; cvta.to.shared.u64 t, %1; cvt.u32.u64 %0, t;}" : "=r"(a) : "l"(p));
    return a;
}
__device__ __forceinline__ void cpasync16(uint32_t s, const void* g) {
    asm volatile("cp.async.cg.shared.global [%0], [%1], 16;\n" :: "r"(s), "l"(g));
}
__device__ __forceinline__ void ldmx4(uint32_t* r, uint32_t a) {
    asm volatile("ldmatrix.sync.aligned.m8n8.x4.shared.b16 {%0,%1,%2,%3}, [%4];"
                 : "=r"(r[0]), "=r"(r[1]), "=r"(r[2]), "=r"(r[3]) : "r"(a));
}
__device__ __forceinline__ void ldmx4t(uint32_t* r, uint32_t a) {
    asm volatile("ldmatrix.sync.aligned.m8n8.x4.trans.shared.b16 {%0,%1,%2,%3}, [%4];"
                 : "=r"(r[0]), "=r"(r[1]), "=r"(r[2]), "=r"(r[3]) : "r"(a));
}
__device__ __forceinline__ void mma16816(float* c, const uint32_t* a, uint32_t b0, uint32_t b1) {
    asm volatile(
        "mma.sync.aligned.m16n8k16.row.col.f32.f16.f16.f32 "
        "{%0,%1,%2,%3}, {%4,%5,%6,%7}, {%8,%9}, {%0,%1,%2,%3};\n"
        : "+f"(c[0]), "+f"(c[1]), "+f"(c[2]), "+f"(c[3])
        : "r"(a[0]), "r"(a[1]), "r"(a[2]), "r"(a[3]), "r"(b0), "r"(b1));
}
__device__ __forceinline__ float sigm(float v) { return 1.0f / (1.0f + expf(-v)); }

// ---------------- conversion kernels ----------------
__global__ __launch_bounds__(256) void conv_xh(
    const float* __restrict__ x, const float* __restrict__ h)
{
    size_t i = ((size_t)blockIdx.x * 256 + threadIdx.x) * 8;   // over 8192*4096
    int m = (int)(i >> 12);
    int c = (int)(i & 4095);
    const float* src = (c < 2048) ? (x + (size_t)m * HID + c)
                                  : (h + (size_t)m * HID + (c - 2048));
    float4 v0 = *(const float4*)(src);
    float4 v1 = *(const float4*)(src + 4);
    __half2 o[4];
    o[0] = __floats2half2_rn(v0.x, v0.y);
    o[1] = __floats2half2_rn(v0.z, v0.w);
    o[2] = __floats2half2_rn(v1.x, v1.y);
    o[3] = __floats2half2_rn(v1.z, v1.w);
    *(uint4*)&g_xh[i] = *(uint4*)o;
}

__global__ __launch_bounds__(256) void conv_w(
    const float* __restrict__ Wf, const float* __restrict__ Wi,
    const float* __restrict__ Wc, const float* __restrict__ Wo)
{
    const int g = blockIdx.y;
    const float* W = (g == 0) ? Wf : (g == 1) ? Wi : (g == 2) ? Wc : Wo;
    size_t i = ((size_t)blockIdx.x * 256 + threadIdx.x) * 8;   // over 4096*2048
    float4 v0 = *(const float4*)(W + i);
    float4 v1 = *(const float4*)(W + i + 4);
    __half2 o[4];
    o[0] = __floats2half2_rn(v0.x, v0.y);
    o[1] = __floats2half2_rn(v0.z, v0.w);
    o[2] = __floats2half2_rn(v1.x, v1.y);
    o[3] = __floats2half2_rn(v1.z, v1.w);
    *(uint4*)&g_w16[(size_t)g * KDIM * HID + i] = *(uint4*)o;
}

// ---------------- fused GEMM + LSTM ----------------
__global__ __launch_bounds__(256, 1) void lstm_mma(
    const float* __restrict__ c_prev,
    const float* __restrict__ bf, const float* __restrict__ bi,
    const float* __restrict__ bc, const float* __restrict__ bo,
    float* __restrict__ out)
{
    extern __shared__ char smem[];
    const uint32_t sbase = s2u(smem);

    const int tid = threadIdx.x;
    const int wid = tid >> 5;
    const int lane = tid & 31;
    const int m_base = blockIdx.y * BM;
    const int n0 = blockIdx.x * NLOC;

    const int wm = (wid & 1) * 64;     // 2 warps along M (64 rows each)
    const int wgrp = wid >> 1;         // 4 warps along within-gate N (16 cols each)

    float acc[4][8][4];
    #pragma unroll
    for (int a = 0; a < 4; ++a)
        #pragma unroll
        for (int b = 0; b < 8; ++b)
            #pragma unroll
            for (int c = 0; c < 4; ++c) acc[a][b][c] = 0.0f;

    // ---- gmem -> smem stage loader ----
    // A: 512 x 16B chunks (128 rows x 64B), 2 per thread
    // B: 1024 x 16B chunks (32 rows x 4 gates x 64B), 4 per thread
    auto load_stage = [&](int s, int kt) {
        const int k0 = kt * BK;
        const uint32_t ab = sbase + s * STAGE_B;
        const uint32_t bb = ab + A_BYTES;
        #pragma unroll
        for (int i = 0; i < 2; ++i) {
            int c = i * 256 + tid;
            int r = c >> 2, cc = c & 3;
            cpasync16(ab + r * A_ROW_B + cc * 16,
                      &g_xh[(size_t)(m_base + r) * KDIM + k0 + cc * 8]);
        }
        #pragma unroll
        for (int i = 0; i < 4; ++i) {
            int c = i * 256 + tid;
            int k = c >> 5, w = c & 31;
            int g = w >> 3, cj = w & 7;
            int scol = (cj >> 1) * 64 + g * 16 + (cj & 1) * 8;
            cpasync16(bb + k * B_ROW_B + scol * 2,
                      &g_w16[((size_t)g * KDIM + k0 + k) * HID + n0 + cj * 8]);
        }
        asm volatile("cp.async.commit_group;\n");
    };

    load_stage(0, 0);
    load_stage(1, 1);
    load_stage(2, 2);

    const int lrow = lane & 15;
    const int lcb = lane >> 4;

    for (int kt = 0; kt < KT; ++kt) {
        if (kt <= KT - 3)      asm volatile("cp.async.wait_group 2;\n");
        else if (kt == KT - 2) asm volatile("cp.async.wait_group 1;\n");
        else                   asm volatile("cp.async.wait_group 0;\n");
        __syncthreads();

        const uint32_t ab = sbase + (kt % STAGES) * STAGE_B;
        const uint32_t bb = ab + A_BYTES;

        #pragma unroll
        for (int ks = 0; ks < 2; ++ks) {
            uint32_t af[4][4], bfr[4][4];
            #pragma unroll
            for (int mf = 0; mf < 4; ++mf)
                ldmx4(af[mf], ab + (wm + mf * 16 + lrow) * A_ROW_B + ks * 32 + lcb * 16);
            #pragma unroll
            for (int g = 0; g < 4; ++g)
                ldmx4t(bfr[g], bb + (ks * 16 + lrow) * B_ROW_B +
                               (wgrp * 64 + g * 16) * 2 + lcb * 16);
            #pragma unroll
            for (int g = 0; g < 4; ++g)
                #pragma unroll
                for (int nsub = 0; nsub < 2; ++nsub)
                    #pragma unroll
                    for (int mf = 0; mf < 4; ++mf)
                        mma16816(acc[mf][g * 2 + nsub], af[mf],
                                 bfr[g][nsub * 2], bfr[g][nsub * 2 + 1]);
        }

        if (kt + 3 < KT) load_stage((kt + 3) % STAGES, kt + 3);
    }

    // ---- fused epilogue ----
    #pragma unroll
    for (int nsub = 0; nsub < 2; ++nsub) {
        const int col = n0 + wgrp * 16 + nsub * 8 + 2 * (lane & 3);
        const float2 bfv = *(const float2*)&bf[col];
        const float2 biv = *(const float2*)&bi[col];
        const float2 bcv = *(const float2*)&bc[col];
        const float2 bov = *(const float2*)&bo[col];
        #pragma unroll
        for (int mf = 0; mf < 4; ++mf) {
            const int r0 = m_base + wm + mf * 16 + (lane >> 2);
            #pragma unroll
            for (int hs = 0; hs < 2; ++hs) {
                const int r = r0 + hs * 8;
                const float2 cpv = *(const float2*)&c_prev[(size_t)r * HID + col];
                float hv[2], cv[2];
                #pragma unroll
                for (int e = 0; e < 2; ++e) {
                    const int ei = hs * 2 + e;
                    float zf = acc[mf][0 + nsub][ei] + ((const float*)&bfv)[e];
                    float zi = acc[mf][2 + nsub][ei] + ((const float*)&biv)[e];
                    float zc = acc[mf][4 + nsub][ei] + ((const float*)&bcv)[e];
                    float zo = acc[mf][6 + nsub][ei] + ((const float*)&bov)[e];
                    float f_t = sigm(zf);
                    float i_t = sigm(zi);
                    float cop = tanhf(zc);
                    float c_t = ((const float*)&cpv)[e] * f_t + i_t * cop;
                    float o_t = sigm(zo);
                    cv[e] = c_t;
                    hv[e] = o_t * tanhf(c_t);
                }
                *(float2*)&out[(size_t)r * HID + col] = make_float2(hv[0], hv[1]);
                *(float2*)&out[(size_t)B_DIM * HID + (size_t)r * HID + col] =
                    make_float2(cv[0], cv[1]);
            }
        }
    }
}

extern "C" void kernel_launch(void* const* d_in, const int* in_sizes, int n_in,
                              void* d_out, int out_size) {
    const float* x      = (const float*)d_in[0];
    const float* h_prev = (const float*)d_in[1];
    const float* c_prev = (const float*)d_in[2];
    // d_in[3] embedding_vec ignored (vanilla mode)
    const float* Wf = (const float*)d_in[4];
    const float* Wi = (const float*)d_in[5];
    const float* Wc = (const float*)d_in[6];
    const float* Wo = (const float*)d_in[7];
    const float* bf = (const float*)d_in[8];
    const float* bi = (const float*)d_in[9];
    const float* bc = (const float*)d_in[10];
    const float* bo = (const float*)d_in[11];
    float* out = (float*)d_out;

    conv_xh<<<(B_DIM * (size_t)KDIM) / (256 * 8), 256>>>(x, h_prev);
    conv_w<<<dim3((KDIM * (size_t)HID) / (256 * 8), 4), 256>>>(Wf, Wi, Wc, Wo);

    cudaFuncSetAttribute(lstm_mma, cudaFuncAttributeMaxDynamicSharedMemorySize, SMEM_DYN);
    dim3 grid(HID / NLOC, B_DIM / BM);   // (32, 64)
    lstm_mma<<<grid, 256, SMEM_DYN>>>(c_prev, bf, bi, bc, bo, out);
}